// round 3
// baseline (speedup 1.0000x reference)
#include <cuda_runtime.h>
#include <cstdint>

#define SEQ   2048
#define BATCH 64
#define DIN   128
#define DH    256
#define G3    (3*DH)   // 768

// ---------------- scratch (device globals) ----------------
__device__ float g_gi[(size_t)SEQ * BATCH * G3];       // input gates
__device__ float g_outs[(size_t)SEQ * BATCH * DH];     // all hidden states
__device__ float g_h[2][BATCH * DH];                   // double-buffered h
__device__ float g_scorep[(size_t)SEQ * BATCH * 16];   // per-unit-tile score partials
__device__ float g_scores[SEQ * BATCH];
__device__ float g_wpart[8 * BATCH * DH];              // wsum partials
__device__ unsigned int g_flag[128];                   // [m*16 + ut] = steps completed

// ---------------- helpers ----------------
__device__ __forceinline__ void fma2(unsigned long long& acc,
                                     unsigned long long a,
                                     unsigned long long b) {
    asm volatile("fma.rn.f32x2 %0, %1, %2, %0;" : "+l"(acc) : "l"(a), "l"(b));
}
__device__ __forceinline__ float2 u2f2(unsigned long long v) {
    float2 f;
    asm("mov.b64 {%0, %1}, %2;" : "=f"(f.x), "=f"(f.y) : "l"(v));
    return f;
}
__device__ __forceinline__ unsigned ld_acq(const unsigned* p) {
    unsigned v;
    asm volatile("ld.global.acquire.gpu.u32 %0, [%1];" : "=r"(v) : "l"(p) : "memory");
    return v;
}
__device__ __forceinline__ void st_rel(unsigned* p, unsigned v) {
    asm volatile("st.global.release.gpu.u32 [%0], %1;" :: "l"(p), "r"(v) : "memory");
}

__global__ void k_init() {
    g_flag[threadIdx.x] = 0u;   // 128 threads
}

// ---------------- Phase 1: GI = mask(data) @ W_ih^T + b_ih ----------------
__global__ void __launch_bounds__(256, 1) gi_gemm(const float* __restrict__ X,
                                                  const float* __restrict__ Wih,
                                                  const float* __restrict__ bih) {
    extern __shared__ float sm[];
    float* As = sm;                // 128 x 132
    float* Bs = sm + 128 * 132;    // 128 x 132
    __shared__ unsigned char maskf[128];

    const int tid = threadIdx.x;
    const int n0 = blockIdx.x * 128;
    const int m0 = blockIdx.y * 128;

    if (tid < 128) maskf[tid] = (X[(size_t)(m0 + tid) * DIN + 127] > 0.0f) ? 1 : 0;
    __syncthreads();

#pragma unroll
    for (int it = 0; it < 16; it++) {
        int t = tid + it * 256;
        int r = t >> 5, kk = t & 31;
        float4 va = *(const float4*)&X[(size_t)(m0 + r) * DIN + kk * 4];
        if (maskf[r] && kk >= 8 && kk < 16) va = make_float4(0.f, 0.f, 0.f, 0.f);
        *(float4*)&As[r * 132 + kk * 4] = va;
        float4 vb = *(const float4*)&Wih[(size_t)(n0 + r) * DIN + kk * 4];
        *(float4*)&Bs[r * 132 + kk * 4] = vb;
    }
    __syncthreads();

    const int tx = tid & 15;
    const int ty = tid >> 4;

    unsigned long long acc[8][8];
#pragma unroll
    for (int i = 0; i < 8; i++)
#pragma unroll
        for (int j = 0; j < 8; j++) acc[i][j] = 0ull;

#pragma unroll 8
    for (int p = 0; p < 64; p++) {
        unsigned long long av[8], bv[8];
#pragma unroll
        for (int i = 0; i < 8; i++)
            av[i] = *(const unsigned long long*)&As[(ty + 16 * i) * 132 + 2 * p];
#pragma unroll
        for (int j = 0; j < 8; j++)
            bv[j] = *(const unsigned long long*)&Bs[(tx + 16 * j) * 132 + 2 * p];
#pragma unroll
        for (int i = 0; i < 8; i++)
#pragma unroll
            for (int j = 0; j < 8; j++) fma2(acc[i][j], av[i], bv[j]);
    }

    __syncthreads();
#pragma unroll
    for (int i = 0; i < 8; i++)
#pragma unroll
        for (int j = 0; j < 8; j++) {
            float2 f = u2f2(acc[i][j]);
            As[(ty + 16 * i) * 132 + tx + 16 * j] = f.x + f.y;
        }
    __syncthreads();

#pragma unroll
    for (int it = 0; it < 16; it++) {
        int t = tid + it * 256;
        int r = t >> 5, kk = t & 31;
        float4 c = *(const float4*)&As[r * 132 + kk * 4];
        float4 b = *(const float4*)&bih[n0 + kk * 4];
        c.x += b.x; c.y += b.y; c.z += b.z; c.w += b.w;
        *(float4*)&g_gi[(size_t)(m0 + r) * G3 + n0 + kk * 4] = c;
    }
}

// ---------------- Phase 2: persistent GRU recurrence ----------------
// 128 blocks = 8 batch-groups x 16 unit-tiles. Per-producer flags; each
// half-warp gates, stages, and consumes exactly one producer's h-slice.
__global__ void __launch_bounds__(256, 1) gru_rec(const float* __restrict__ Whh,
                                                  const float* __restrict__ bhh_g,
                                                  const float* __restrict__ watt) {
    extern __shared__ float sm[];
    float* W_sh = sm;                   // 48 x 260
    float* h_sh = sm + 48 * 260;        // 8  x 260
    float* part = h_sh + 8 * 260;       // 384 x 17

    const int tid = threadIdx.x;
    const int ut  = blockIdx.x & 15;
    const int m   = blockIdx.x >> 4;
    const int kc  = tid >> 4;           // 0..15 k-chunk == producer slice
    const int ot  = tid & 15;
    const int bq  = ot >> 3;            // 0..1
    const int rq  = ot & 7;             // 0..7
    const int kbase = kc * 16;
    const int hl  = tid & 15;           // lane within half-warp (== ot)

    // epilogue identity (tid < 128)
    const int eb = tid >> 4;
    const int eu = tid & 15;
    const int ug = ut * 16 + eu;
    const int bg = m * 8 + eb;

    // load W_hh tile once
#pragma unroll
    for (int it = 0; it < 12; it++) {
        int t = tid + it * 256;
        int row = t >> 6, kk = t & 63;
        int g = row >> 4, uu = row & 15;
        float4 v = *(const float4*)&Whh[(size_t)(g * DH + ut * 16 + uu) * DH + kk * 4];
        *(float4*)&W_sh[row * 260 + kk * 4] = v;
    }
    float bhh0 = 0.f, bhh1 = 0.f, bhh2 = 0.f, wattv = 0.f;
    if (tid < 128) {
        bhh0 = bhh_g[0 * DH + ug];
        bhh1 = bhh_g[1 * DH + ug];
        bhh2 = bhh_g[2 * DH + ug];
        wattv = watt[ug];
    }
    unsigned* myflag = &g_flag[m * 16 + kc];
    __syncthreads();

    for (int s = 0; s < SEQ; s++) {
        // prefetch gi (independent of h) — issue before the spin
        float gir = 0.f, giz = 0.f, gin = 0.f;
        if (tid < 128) {
            const size_t base = ((size_t)s * BATCH + bg) * G3 + ug;
            gir = __ldcg(&g_gi[base]);
            giz = __ldcg(&g_gi[base + DH]);
            gin = __ldcg(&g_gi[base + 2 * DH]);
        }

        // gate on my producer, stage my slice (8 batches x 16 units = 32 float4)
        if (s > 0) {
            const unsigned tgt = (unsigned)s;
            while (ld_acq(myflag) < tgt) {}
            const float* hsrc = &g_h[(s - 1) & 1][m * 8 * DH];
#pragma unroll
            for (int it = 0; it < 2; it++) {
                int i = hl + it * 16;          // 0..31
                int bb = i >> 2, fc = i & 3;
                float4 v = __ldcg((const float4*)&hsrc[bb * DH + kbase + fc * 4]);
                *(float4*)&h_sh[bb * 260 + kbase + fc * 4] = v;
            }
        } else {
#pragma unroll
            for (int it = 0; it < 2; it++) {
                int i = hl + it * 16;
                int bb = i >> 2, fc = i & 3;
                *(float4*)&h_sh[bb * 260 + kbase + fc * 4] = make_float4(0.f, 0.f, 0.f, 0.f);
            }
        }
        __syncwarp();

        // partial dot over my k-chunk: 4 batches x 6 rows x 16 k
        unsigned long long acc[4][6];
#pragma unroll
        for (int i = 0; i < 4; i++)
#pragma unroll
            for (int j = 0; j < 6; j++) acc[i][j] = 0ull;

#pragma unroll
        for (int q = 0; q < 4; q++) {
            ulonglong2 hq[4], wq[6];
#pragma unroll
            for (int i = 0; i < 4; i++)
                hq[i] = *(const ulonglong2*)&h_sh[(bq + 2 * i) * 260 + kbase + q * 4];
#pragma unroll
            for (int j = 0; j < 6; j++)
                wq[j] = *(const ulonglong2*)&W_sh[(rq + 8 * j) * 260 + kbase + q * 4];
#pragma unroll
            for (int i = 0; i < 4; i++)
#pragma unroll
                for (int j = 0; j < 6; j++) {
                    fma2(acc[i][j], hq[i].x, wq[j].x);
                    fma2(acc[i][j], hq[i].y, wq[j].y);
                }
        }

#pragma unroll
        for (int i = 0; i < 4; i++)
#pragma unroll
            for (int j = 0; j < 6; j++) {
                float2 f = u2f2(acc[i][j]);
                int o = (bq + 2 * i) * 48 + (rq + 8 * j);
                part[o * 17 + kc] = f.x + f.y;
            }
        __syncthreads();   // all partials in; h_sh(old) stable for epilogue

        float hnew = 0.f;
        if (tid < 128) {
            float Ar = bhh0 + gir, Az = bhh1 + giz, An = bhh2;
            const int or_ = (eb * 48 + eu) * 17;
            const int oz_ = (eb * 48 + 16 + eu) * 17;
            const int on_ = (eb * 48 + 32 + eu) * 17;
#pragma unroll
            for (int c = 0; c < 16; c++) {
                Ar += part[or_ + c];
                Az += part[oz_ + c];
                An += part[on_ + c];
            }
            const float rr = 1.0f / (1.0f + __expf(-Ar));
            const float zz = 1.0f / (1.0f + __expf(-Az));
            const float nn = tanhf(fmaf(rr, An, gin));
            const float hold = h_sh[eb * 260 + ug];
            hnew = fmaf(zz, hold - nn, nn);
            __stcg(&g_h[s & 1][bg * DH + ug], hnew);
        }
        __syncthreads();   // h stores done (and part[] reads done)

        if (tid == 0) st_rel(&g_flag[m * 16 + ut], (unsigned)(s + 1));

        // tail work off the critical path
        if (tid < 128) {
            g_outs[((size_t)s * BATCH + bg) * DH + ug] = hnew;
            float sc = hnew * wattv;
#pragma unroll
            for (int o = 8; o > 0; o >>= 1) sc += __shfl_xor_sync(0xffffffffu, sc, o);
            if (eu == 0) g_scorep[((size_t)s * BATCH + bg) * 16 + ut] = sc;
        }
    }
}

// ---------------- Phase 3: attention ----------------
__global__ void k_scores_red() {
    const int idx = blockIdx.x * 256 + threadIdx.x;
    const float4* p = (const float4*)&g_scorep[(size_t)idx * 16];
    float4 a = p[0], b = p[1], c = p[2], d = p[3];
    g_scores[idx] = (a.x + a.y + a.z + a.w) + (b.x + b.y + b.z + b.w) +
                    (c.x + c.y + c.z + c.w) + (d.x + d.y + d.z + d.w);
}

__global__ void k_softmax() {
    __shared__ float red[256];
    const int b = blockIdx.x, tid = threadIdx.x;
    float mx = -1e30f;
    for (int s = tid; s < SEQ; s += 256) mx = fmaxf(mx, g_scores[s * BATCH + b]);
    red[tid] = mx; __syncthreads();
    for (int o = 128; o > 0; o >>= 1) { if (tid < o) red[tid] = fmaxf(red[tid], red[tid + o]); __syncthreads(); }
    mx = red[0]; __syncthreads();
    float sum = 0.f;
    for (int s = tid; s < SEQ; s += 256) sum += __expf(g_scores[s * BATCH + b] - mx);
    red[tid] = sum; __syncthreads();
    for (int o = 128; o > 0; o >>= 1) { if (tid < o) red[tid] += red[tid + o]; __syncthreads(); }
    const float inv = 1.0f / red[0];
    for (int s = tid; s < SEQ; s += 256)
        g_scores[s * BATCH + b] = __expf(g_scores[s * BATCH + b] - mx) * inv;
}

__global__ void k_wsum1() {
    const int b = blockIdx.x, c = blockIdx.y, h = threadIdx.x;
    float acc = 0.f;
    const int s0 = c * 256;
#pragma unroll 4
    for (int s = s0; s < s0 + 256; s++)
        acc = fmaf(__ldg(&g_scores[s * BATCH + b]),
                   g_outs[((size_t)s * BATCH + b) * DH + h], acc);
    g_wpart[(c * BATCH + b) * DH + h] = acc;
}

__global__ void k_wsum2(float* __restrict__ out) {
    const int b = blockIdx.x, h = threadIdx.x;
    float acc = 0.f;
#pragma unroll
    for (int c = 0; c < 8; c++) acc += g_wpart[(c * BATCH + b) * DH + h];
    out[b * DH + h] = acc;
}

// ---------------- launch ----------------
extern "C" void kernel_launch(void* const* d_in, const int* in_sizes, int n_in,
                              void* d_out, int out_size) {
    const float* data = (const float*)d_in[0];
    const float* Wih  = (const float*)d_in[1];
    const float* Whh  = (const float*)d_in[2];
    const float* bih  = (const float*)d_in[3];
    const float* bhh  = (const float*)d_in[4];
    const float* watt = (const float*)d_in[5];
    float* out = (float*)d_out;

    const int gi_smem  = 2 * 128 * 132 * (int)sizeof(float);                 // 135168
    const int gru_smem = (48 * 260 + 8 * 260 + 384 * 17) * (int)sizeof(float); // 84352

    cudaFuncSetAttribute(gi_gemm, cudaFuncAttributeMaxDynamicSharedMemorySize, gi_smem);
    cudaFuncSetAttribute(gru_rec, cudaFuncAttributeMaxDynamicSharedMemorySize, gru_smem);

    k_init<<<1, 128>>>();
    dim3 gg(G3 / 128, (SEQ * BATCH) / 128);   // (6, 1024)
    gi_gemm<<<gg, 256, gi_smem>>>(data, Wih, bih);
    gru_rec<<<128, 256, gru_smem>>>(Whh, bhh, watt);
    k_scores_red<<<(SEQ * BATCH) / 256, 256>>>();
    k_softmax<<<BATCH, 256>>>();
    dim3 gw(BATCH, 8);
    k_wsum1<<<gw, 256>>>();
    k_wsum2<<<BATCH, 256>>>(out);
}

// round 4
// speedup vs baseline: 1.2431x; 1.2431x over previous
#include <cuda_runtime.h>
#include <cstdint>

#define SEQ   2048
#define BATCH 64
#define DIN   128
#define DH    256
#define G3    (3*DH)   // 768

#define CLU   8        // CTAs per cluster (= unit tiles per group)
#define NG    16       // batch groups (clusters)
#define BPG   4        // batches per group
#define UPB   32       // hidden units per block
#define ROWSB 96       // 3 gates * UPB
#define HPAD  260      // padded row stride (floats)
#define HBUF  (BPG*HPAD)  // 1040 floats per h buffer

// ---------------- scratch (device globals) ----------------
__device__ float g_gi[(size_t)SEQ * BATCH * G3];
__device__ float g_outs[(size_t)SEQ * BATCH * DH];
__device__ float g_scorep[(size_t)SEQ * BATCH * CLU];
__device__ float g_scores[SEQ * BATCH];
__device__ float g_wpart[8 * BATCH * DH];

// ---------------- helpers ----------------
__device__ __forceinline__ void fma2(unsigned long long& acc,
                                     unsigned long long a,
                                     unsigned long long b) {
    asm volatile("fma.rn.f32x2 %0, %1, %2, %0;" : "+l"(acc) : "l"(a), "l"(b));
}
__device__ __forceinline__ float2 u2f2(unsigned long long v) {
    float2 f;
    asm("mov.b64 {%0, %1}, %2;" : "=f"(f.x), "=f"(f.y) : "l"(v));
    return f;
}
__device__ __forceinline__ uint32_t smem_u32(const void* p) {
    return (uint32_t)__cvta_generic_to_shared(p);
}
__device__ __forceinline__ uint32_t cluster_rank() {
    uint32_t r; asm("mov.u32 %0, %%cluster_ctarank;" : "=r"(r)); return r;
}
__device__ __forceinline__ uint32_t mapa_sh(uint32_t local, uint32_t rank) {
    uint32_t r;
    asm("mapa.shared::cluster.u32 %0, %1, %2;" : "=r"(r) : "r"(local), "r"(rank));
    return r;
}
__device__ __forceinline__ void mbar_init(uint32_t a, uint32_t cnt) {
    asm volatile("mbarrier.init.shared.b64 [%0], %1;" :: "r"(a), "r"(cnt) : "memory");
}
__device__ __forceinline__ void mbar_expect_tx(uint32_t a, uint32_t tx) {
    asm volatile("mbarrier.arrive.expect_tx.shared.b64 _, [%0], %1;"
                 :: "r"(a), "r"(tx) : "memory");
}
__device__ __forceinline__ void mbar_arrive_remote(uint32_t a) {
    asm volatile("mbarrier.arrive.release.cluster.shared::cluster.b64 _, [%0];"
                 :: "r"(a) : "memory");
}
__device__ __forceinline__ void st_async_f32(uint32_t raddr, float v, uint32_t rmbar) {
    asm volatile("st.async.weak.shared::cluster.mbarrier::complete_tx::bytes.b32 [%0], %1, [%2];"
                 :: "r"(raddr), "r"(__float_as_uint(v)), "r"(rmbar) : "memory");
}
__device__ __forceinline__ void mbar_wait(uint32_t a, uint32_t ph) {
    uint32_t done;
    asm volatile(
        "{\n\t.reg .pred P;\n\t"
        "mbarrier.try_wait.parity.acquire.cluster.shared::cta.b64 P, [%1], %2;\n\t"
        "selp.b32 %0, 1, 0, P;\n\t}"
        : "=r"(done) : "r"(a), "r"(ph) : "memory");
    while (!done) {
        asm volatile(
            "{\n\t.reg .pred P;\n\t"
            "mbarrier.try_wait.parity.acquire.cluster.shared::cta.b64 P, [%1], %2, 0x989680;\n\t"
            "selp.b32 %0, 1, 0, P;\n\t}"
            : "=r"(done) : "r"(a), "r"(ph) : "memory");
    }
}
#define CLUSTER_SYNC_() do { \
    asm volatile("barrier.cluster.arrive.aligned;" ::: "memory"); \
    asm volatile("barrier.cluster.wait.aligned;" ::: "memory"); \
} while (0)

// ---------------- Phase 1: GI = mask(data) @ W_ih^T + b_ih ----------------
__global__ void __launch_bounds__(256, 1) gi_gemm(const float* __restrict__ X,
                                                  const float* __restrict__ Wih,
                                                  const float* __restrict__ bih) {
    extern __shared__ float sm[];
    float* As = sm;                // 128 x 132
    float* Bs = sm + 128 * 132;    // 128 x 132
    __shared__ unsigned char maskf[128];

    const int tid = threadIdx.x;
    const int n0 = blockIdx.x * 128;
    const int m0 = blockIdx.y * 128;

    if (tid < 128) maskf[tid] = (X[(size_t)(m0 + tid) * DIN + 127] > 0.0f) ? 1 : 0;
    __syncthreads();

#pragma unroll
    for (int it = 0; it < 16; it++) {
        int t = tid + it * 256;
        int r = t >> 5, kk = t & 31;
        float4 va = *(const float4*)&X[(size_t)(m0 + r) * DIN + kk * 4];
        if (maskf[r] && kk >= 8 && kk < 16) va = make_float4(0.f, 0.f, 0.f, 0.f);
        *(float4*)&As[r * 132 + kk * 4] = va;
        float4 vb = *(const float4*)&Wih[(size_t)(n0 + r) * DIN + kk * 4];
        *(float4*)&Bs[r * 132 + kk * 4] = vb;
    }
    __syncthreads();

    const int tx = tid & 15;
    const int ty = tid >> 4;

    unsigned long long acc[8][8];
#pragma unroll
    for (int i = 0; i < 8; i++)
#pragma unroll
        for (int j = 0; j < 8; j++) acc[i][j] = 0ull;

#pragma unroll 8
    for (int p = 0; p < 64; p++) {
        unsigned long long av[8], bv[8];
#pragma unroll
        for (int i = 0; i < 8; i++)
            av[i] = *(const unsigned long long*)&As[(ty + 16 * i) * 132 + 2 * p];
#pragma unroll
        for (int j = 0; j < 8; j++)
            bv[j] = *(const unsigned long long*)&Bs[(tx + 16 * j) * 132 + 2 * p];
#pragma unroll
        for (int i = 0; i < 8; i++)
#pragma unroll
            for (int j = 0; j < 8; j++) fma2(acc[i][j], av[i], bv[j]);
    }

    __syncthreads();
#pragma unroll
    for (int i = 0; i < 8; i++)
#pragma unroll
        for (int j = 0; j < 8; j++) {
            float2 f = u2f2(acc[i][j]);
            As[(ty + 16 * i) * 132 + tx + 16 * j] = f.x + f.y;
        }
    __syncthreads();

#pragma unroll
    for (int it = 0; it < 16; it++) {
        int t = tid + it * 256;
        int r = t >> 5, kk = t & 31;
        float4 c = *(const float4*)&As[r * 132 + kk * 4];
        float4 b = *(const float4*)&bih[n0 + kk * 4];
        c.x += b.x; c.y += b.y; c.z += b.z; c.w += b.w;
        *(float4*)&g_gi[(size_t)(m0 + r) * G3 + n0 + kk * 4] = c;
    }
}

// ---------------- Phase 2: persistent GRU, cluster-of-8 per batch group ----
// h lives only in SMEM; producers push hnew into every cluster CTA's h buffer
// via st.async (tx-counted mbarrier), consumers wake on try_wait.
__global__ void __launch_bounds__(256, 1) __cluster_dims__(CLU, 1, 1)
gru_rec(const float* __restrict__ Whh,
        const float* __restrict__ bhh_g,
        const float* __restrict__ watt) {
    extern __shared__ float sm[];
    float* W_sh = sm;                        // 96 x 260
    float* h_sh = sm + ROWSB * HPAD;         // 2 x 1040
    float* part = h_sh + 2 * HBUF;           // 384 x 17

    __shared__ __align__(8) unsigned long long mbar[4];  // full0 full1 empty0 empty1

    const int tid = threadIdx.x;
    const uint32_t rank = cluster_rank();    // unit tile 0..7
    const int ut = (int)rank;
    const int m  = blockIdx.x >> 3;          // group 0..15

    const int kc = tid >> 4;                 // 0..15 k-chunk
    const int rq = tid & 15;                 // row group
    const int kbase = kc * 16;

    const int eb = tid >> 5;                 // epilogue: batch 0..3 (tid<128)
    const int eu = tid & 31;                 // epilogue: unit 0..31
    const int ug = ut * UPB + eu;            // global hidden unit
    const int bg = m * BPG + eb;             // global batch

    const uint32_t mb_local = smem_u32(mbar);
    const uint32_t h_local  = smem_u32(h_sh);

    // barriers: full[p] count=1 (consumer expect) + 4096B tx; empty[p] count=8
    if (tid == 0) {
        mbar_init(mb_local + 0, 1);
        mbar_init(mb_local + 8, 1);
        mbar_init(mb_local + 16, 8);
        mbar_init(mb_local + 24, 8);
    }
    // zero h buffer 0 (used at s=0)
    for (int i = tid; i < HBUF; i += 256) h_sh[i] = 0.0f;

    // load W_hh tile: local row = g*32+u  ->  Whh[g*256 + ut*32 + u]
#pragma unroll
    for (int it = 0; it < 24; it++) {
        int t = tid + it * 256;              // 0..6143 float4 slots
        int row = t >> 6, kk = t & 63;
        int g = row >> 5, uu = row & 31;
        float4 v = *(const float4*)&Whh[(size_t)(g * DH + ut * UPB + uu) * DH + kk * 4];
        *(float4*)&W_sh[row * HPAD + kk * 4] = v;
    }
    float bhh0 = 0.f, bhh1 = 0.f, bhh2 = 0.f, wattv = 0.f;
    if (tid < 128) {
        bhh0 = bhh_g[0 * DH + ug];
        bhh1 = bhh_g[1 * DH + ug];
        bhh2 = bhh_g[2 * DH + ug];
        wattv = watt[ug];
    }
    __syncthreads();
    if (tid == 0) {               // pre-post expects for phase 0 of both fulls
        mbar_expect_tx(mb_local + 0, 4096);
        mbar_expect_tx(mb_local + 8, 4096);
    }

    // precompute peer addresses
    uint32_t peer_h[CLU], peer_mb[CLU];
#pragma unroll
    for (int r = 0; r < CLU; r++) {
        peer_h[r]  = mapa_sh(h_local, (uint32_t)r);
        peer_mb[r] = mapa_sh(mb_local, (uint32_t)r);
    }
    const uint32_t my_off = (uint32_t)((eb * HPAD + ug) * 4);

    CLUSTER_SYNC_();   // barriers initialized + expects posted everywhere

    for (int s = 0; s < SEQ; s++) {
        const int p  = s & 1;
        const int pn = p ^ 1;
        const uint32_t pw = (uint32_t)(((s - 1) >> 1) & 1);

        // prefetch gi (independent of h)
        float gir = 0.f, giz = 0.f, gin = 0.f;
        if (tid < 128) {
            const size_t base = ((size_t)s * BATCH + bg) * G3 + ug;
            gir = __ldcg(&g_gi[base]);
            giz = __ldcg(&g_gi[base + DH]);
            gin = __ldcg(&g_gi[base + 2 * DH]);
        }

        if (s > 0) {
            mbar_wait(mb_local + (uint32_t)(p * 8), pw);      // h(s-1) fully arrived
            if (tid == 0 && s + 2 < SEQ)                      // re-arm phase for s+2
                mbar_expect_tx(mb_local + (uint32_t)(p * 8), 4096);
        }

        // partial dots: 4 batches x 6 rows (rq + 16j) x 16 k
        const float* hb = h_sh + p * HBUF;
        unsigned long long acc[4][6];
#pragma unroll
        for (int i = 0; i < 4; i++)
#pragma unroll
            for (int j = 0; j < 6; j++) acc[i][j] = 0ull;

#pragma unroll
        for (int q = 0; q < 4; q++) {
            ulonglong2 hq[4], wq[6];
#pragma unroll
            for (int i = 0; i < 4; i++)
                hq[i] = *(const ulonglong2*)&hb[i * HPAD + kbase + q * 4];
#pragma unroll
            for (int j = 0; j < 6; j++)
                wq[j] = *(const ulonglong2*)&W_sh[(rq + 16 * j) * HPAD + kbase + q * 4];
#pragma unroll
            for (int i = 0; i < 4; i++)
#pragma unroll
                for (int j = 0; j < 6; j++) {
                    fma2(acc[i][j], hq[i].x, wq[j].x);
                    fma2(acc[i][j], hq[i].y, wq[j].y);
                }
        }

#pragma unroll
        for (int i = 0; i < 4; i++)
#pragma unroll
            for (int j = 0; j < 6; j++) {
                float2 f = u2f2(acc[i][j]);
                part[(i * ROWSB + rq + 16 * j) * 17 + kc] = f.x + f.y;
            }
        __syncthreads();

        float hnew = 0.f;
        if (tid < 128) {
            float Ar = bhh0 + gir, Az = bhh1 + giz, An = bhh2;
            const int o_r = (eb * ROWSB + eu) * 17;
            const int o_z = (eb * ROWSB + UPB + eu) * 17;
            const int o_n = (eb * ROWSB + 2 * UPB + eu) * 17;
#pragma unroll
            for (int c = 0; c < 16; c++) {
                Ar += part[o_r + c];
                Az += part[o_z + c];
                An += part[o_n + c];
            }
            const float rr = 1.0f / (1.0f + __expf(-Ar));
            const float zz = 1.0f / (1.0f + __expf(-Az));
            const float nn = tanhf(fmaf(rr, An, gin));
            const float hold = h_sh[p * HBUF + eb * HPAD + ug];
            hnew = fmaf(zz, hold - nn, nn);

            if (s + 1 < SEQ) {
                if (s > 0)   // backpressure: everyone done reading buf pn (step s-1)
                    mbar_wait(mb_local + 16 + (uint32_t)(pn * 8), pw);
                const uint32_t off = (uint32_t)(pn * HBUF * 4) + my_off;
                const uint32_t mboff = (uint32_t)(pn * 8);
#pragma unroll
                for (int r = 0; r < CLU; r++)
                    st_async_f32(peer_h[r] + off, hnew, peer_mb[r] + mboff);
            }
        }
        __syncthreads();   // all reads of buf p complete (incl. hold)

        if (tid == 0 && s + 2 < SEQ) {   // announce "done reading buf p"
#pragma unroll
            for (int r = 0; r < CLU; r++)
                mbar_arrive_remote(peer_mb[r] + 16 + (uint32_t)(p * 8));
        }

        // tail (off critical path)
        if (tid < 128) {
            g_outs[((size_t)s * BATCH + bg) * DH + ug] = hnew;
            float sc = hnew * wattv;
#pragma unroll
            for (int o = 16; o > 0; o >>= 1) sc += __shfl_xor_sync(0xffffffffu, sc, o);
            if (eu == 0) g_scorep[((size_t)s * BATCH + bg) * CLU + ut] = sc;
        }
    }

    __syncthreads();
    CLUSTER_SYNC_();   // all in-flight remote ops land before any CTA exits
}

// ---------------- Phase 3: attention ----------------
__global__ void k_scores_red() {
    const int idx = blockIdx.x * 256 + threadIdx.x;
    const float4* p = (const float4*)&g_scorep[(size_t)idx * CLU];
    float4 a = p[0], b = p[1];
    g_scores[idx] = (a.x + a.y + a.z + a.w) + (b.x + b.y + b.z + b.w);
}

__global__ void k_softmax() {
    __shared__ float red[256];
    const int b = blockIdx.x, tid = threadIdx.x;
    float mx = -1e30f;
    for (int s = tid; s < SEQ; s += 256) mx = fmaxf(mx, g_scores[s * BATCH + b]);
    red[tid] = mx; __syncthreads();
    for (int o = 128; o > 0; o >>= 1) { if (tid < o) red[tid] = fmaxf(red[tid], red[tid + o]); __syncthreads(); }
    mx = red[0]; __syncthreads();
    float sum = 0.f;
    for (int s = tid; s < SEQ; s += 256) sum += __expf(g_scores[s * BATCH + b] - mx);
    red[tid] = sum; __syncthreads();
    for (int o = 128; o > 0; o >>= 1) { if (tid < o) red[tid] += red[tid + o]; __syncthreads(); }
    const float inv = 1.0f / red[0];
    for (int s = tid; s < SEQ; s += 256)
        g_scores[s * BATCH + b] = __expf(g_scores[s * BATCH + b] - mx) * inv;
}

__global__ void k_wsum1() {
    const int b = blockIdx.x, c = blockIdx.y, h = threadIdx.x;
    float acc = 0.f;
    const int s0 = c * 256;
#pragma unroll 4
    for (int s = s0; s < s0 + 256; s++)
        acc = fmaf(__ldg(&g_scores[s * BATCH + b]),
                   g_outs[((size_t)s * BATCH + b) * DH + h], acc);
    g_wpart[(c * BATCH + b) * DH + h] = acc;
}

__global__ void k_wsum2(float* __restrict__ out) {
    const int b = blockIdx.x, h = threadIdx.x;
    float acc = 0.f;
#pragma unroll
    for (int c = 0; c < 8; c++) acc += g_wpart[(c * BATCH + b) * DH + h];
    out[b * DH + h] = acc;
}

// ---------------- launch ----------------
extern "C" void kernel_launch(void* const* d_in, const int* in_sizes, int n_in,
                              void* d_out, int out_size) {
    const float* data = (const float*)d_in[0];
    const float* Wih  = (const float*)d_in[1];
    const float* Whh  = (const float*)d_in[2];
    const float* bih  = (const float*)d_in[3];
    const float* bhh  = (const float*)d_in[4];
    const float* watt = (const float*)d_in[5];
    float* out = (float*)d_out;

    const int gi_smem  = 2 * 128 * 132 * (int)sizeof(float);                       // 135168
    const int gru_smem = (ROWSB * HPAD + 2 * HBUF + 384 * 17) * (int)sizeof(float); // 134272

    cudaFuncSetAttribute(gi_gemm, cudaFuncAttributeMaxDynamicSharedMemorySize, gi_smem);
    cudaFuncSetAttribute(gru_rec, cudaFuncAttributeMaxDynamicSharedMemorySize, gru_smem);

    dim3 gg(G3 / 128, (SEQ * BATCH) / 128);   // (6, 1024)
    gi_gemm<<<gg, 256, gi_smem>>>(data, Wih, bih);
    gru_rec<<<NG * CLU, 256, gru_smem>>>(Whh, bhh, watt);
    k_scores_red<<<(SEQ * BATCH) / 256, 256>>>();
    k_softmax<<<BATCH, 256>>>();
    dim3 gw(BATCH, 8);
    k_wsum1<<<gw, 256>>>();
    k_wsum2<<<BATCH, 256>>>(out);
}